// round 8
// baseline (speedup 1.0000x reference)
#include <cuda_runtime.h>
#include <cuda_bf16.h>
#include <cstdint>

// Unfold3d: x (B=4, C=32, D=16, H=48, W=48) fp32, K=3, PAD=1, STR=1, DIL=1.
// out[b][c*27 + kidx][d*HW + h*W + w] = x[b][c][d+kd-1][h+kh-1][w+kw-1] (0 OOB)
//
// R7: (a) persistent grid of exactly 8 CTAs/SM x 148 SMs = 1184 CTAs looping
// over the 2048 (d, bc) tiles -- removes the 1.73-wave quantization tail;
// (b) plain write-back float4 stores instead of __stcs -- tests whether L2
// dirty-line aggregation schedules DRAM writes better than evict-first.
// Otherwise the R5 structure: packed halo-free smem planes (27.6KB ->
// 8 CTAs/SM), predicated row/col edges, 1 LDS.128 + 2 scalar LDS per 3 stores.

#define B_  4
#define C_  32
#define D_  16
#define H_  48
#define W_  48
#define HW  (H_ * W_)          // 2304
#define DHW (D_ * HW)          // 36864
#define W4  (W_ / 4)           // 12
#define SPLANE HW              // packed plane, 2304 floats
#define SMEM_FLOATS (3 * SPLANE)  // 6912 floats = 27648 B

#define NTILES (D_ * B_ * C_)  // 2048
#define NCTAS  1184            // 148 SMs * 8 CTAs

__global__ __launch_bounds__(192, 8) void unfold3d_kernel(
    const float* __restrict__ x, float* __restrict__ out)
{
    __shared__ float s[SMEM_FLOATS];

    const int w4 = threadIdx.x;         // 0..11
    const int hb = threadIdx.y;         // 0..15

    for (int tile = blockIdx.x; tile < NTILES; tile += NCTAS) {
        const int d  = tile & 15;       // 0..15
        const int bc = tile >> 4;       // 0..127

        // ---- Phase 1: copy 3 planes (d-1, d, d+1) into packed smem ----
        {
            const float* __restrict__ xb = x + (size_t)bc * DHW;
            #pragma unroll
            for (int p = 0; p < 3; p++) {
                const int dd = d + p - 1;
                float* __restrict__ sp = s + p * SPLANE;
                if ((unsigned)dd < (unsigned)D_) {
                    const float* __restrict__ plane = xb + dd * HW;
                    #pragma unroll
                    for (int k = 0; k < 3; k++) {
                        const int r = hb + k * 16;
                        *reinterpret_cast<float4*>(sp + r * W_ + w4 * 4) =
                            *reinterpret_cast<const float4*>(
                                plane + r * W_ + w4 * 4);
                    }
                } else {
                    #pragma unroll
                    for (int k = 0; k < 3; k++) {
                        const int r = hb + k * 16;
                        *reinterpret_cast<float4*>(sp + r * W_ + w4 * 4) =
                            make_float4(0.f, 0.f, 0.f, 0.f);
                    }
                }
            }
        }
        __syncthreads();

        // ---- Phase 2: 27 channel tiles, predicated edges ----
        float* __restrict__ ob = out + (size_t)bc * 27 * DHW + (size_t)d * HW;

        #pragma unroll
        for (int k = 0; k < 3; k++) {
            const int h = hb + k * 16;                    // 0..47
            float* __restrict__ obase = ob + h * W_ + w4 * 4;

            #pragma unroll
            for (int kh = 0; kh < 3; kh++) {
                const int hh = h + kh - 1;                // -1..48
                const bool rok = (unsigned)hh < (unsigned)H_;

                #pragma unroll
                for (int kd = 0; kd < 3; kd++) {
                    const float* __restrict__ p =
                        s + kd * SPLANE + hh * W_ + w4 * 4;

                    float4 q = make_float4(0.f, 0.f, 0.f, 0.f);
                    float pw = 0.f, nx = 0.f;
                    if (rok) {
                        q = *reinterpret_cast<const float4*>(p);
                        if (w4 > 0)       pw = p[-1];     // input col 4w4-1
                        if (w4 < W4 - 1)  nx = p[4];      // input col 4w4+4
                    }

                    float* o = obase + ((kd * 3 + kh) * 3) * DHW;
                    *reinterpret_cast<float4*>(o) =
                        make_float4(pw, q.x, q.y, q.z);            // kw=0
                    *reinterpret_cast<float4*>(o + DHW) = q;       // kw=1
                    *reinterpret_cast<float4*>(o + 2 * DHW) =
                        make_float4(q.y, q.z, q.w, nx);            // kw=2
                }
            }
        }
        __syncthreads();   // protect smem before next tile overwrites it
    }
}

extern "C" void kernel_launch(void* const* d_in, const int* in_sizes, int n_in,
                              void* d_out, int out_size)
{
    const float* x = (const float*)d_in[0];
    float* out = (float*)d_out;

    dim3 grid(NCTAS);              // 1184 persistent CTAs (8 per SM)
    dim3 block(W4, 16);            // 192 threads
    unfold3d_kernel<<<grid, block>>>(x, out);
}

// round 9
// speedup vs baseline: 1.0075x; 1.0075x over previous
#include <cuda_runtime.h>
#include <cuda_bf16.h>
#include <cstdint>

// Unfold3d: x (B=4, C=32, D=16, H=48, W=48) fp32, K=3, PAD=1, STR=1, DIL=1.
// out[b][c*27 + kidx][d*HW + h*W + w] = x[b][c][d+kd-1][h+kh-1][w+kw-1] (0 OOB)
//
// R7: (a) persistent grid of exactly 8 CTAs/SM x 148 SMs = 1184 CTAs looping
// over the 2048 (d, bc) tiles -- removes the 1.73-wave quantization tail;
// (b) plain write-back float4 stores instead of __stcs -- tests whether L2
// dirty-line aggregation schedules DRAM writes better than evict-first.
// Otherwise the R5 structure: packed halo-free smem planes (27.6KB ->
// 8 CTAs/SM), predicated row/col edges, 1 LDS.128 + 2 scalar LDS per 3 stores.

#define B_  4
#define C_  32
#define D_  16
#define H_  48
#define W_  48
#define HW  (H_ * W_)          // 2304
#define DHW (D_ * HW)          // 36864
#define W4  (W_ / 4)           // 12
#define SPLANE HW              // packed plane, 2304 floats
#define SMEM_FLOATS (3 * SPLANE)  // 6912 floats = 27648 B

#define NTILES (D_ * B_ * C_)  // 2048
#define NCTAS  1184            // 148 SMs * 8 CTAs

__global__ __launch_bounds__(192, 8) void unfold3d_kernel(
    const float* __restrict__ x, float* __restrict__ out)
{
    __shared__ float s[SMEM_FLOATS];

    const int w4 = threadIdx.x;         // 0..11
    const int hb = threadIdx.y;         // 0..15

    for (int tile = blockIdx.x; tile < NTILES; tile += NCTAS) {
        const int d  = tile & 15;       // 0..15
        const int bc = tile >> 4;       // 0..127

        // ---- Phase 1: copy 3 planes (d-1, d, d+1) into packed smem ----
        {
            const float* __restrict__ xb = x + (size_t)bc * DHW;
            #pragma unroll
            for (int p = 0; p < 3; p++) {
                const int dd = d + p - 1;
                float* __restrict__ sp = s + p * SPLANE;
                if ((unsigned)dd < (unsigned)D_) {
                    const float* __restrict__ plane = xb + dd * HW;
                    #pragma unroll
                    for (int k = 0; k < 3; k++) {
                        const int r = hb + k * 16;
                        *reinterpret_cast<float4*>(sp + r * W_ + w4 * 4) =
                            *reinterpret_cast<const float4*>(
                                plane + r * W_ + w4 * 4);
                    }
                } else {
                    #pragma unroll
                    for (int k = 0; k < 3; k++) {
                        const int r = hb + k * 16;
                        *reinterpret_cast<float4*>(sp + r * W_ + w4 * 4) =
                            make_float4(0.f, 0.f, 0.f, 0.f);
                    }
                }
            }
        }
        __syncthreads();

        // ---- Phase 2: 27 channel tiles, predicated edges ----
        float* __restrict__ ob = out + (size_t)bc * 27 * DHW + (size_t)d * HW;

        #pragma unroll
        for (int k = 0; k < 3; k++) {
            const int h = hb + k * 16;                    // 0..47
            float* __restrict__ obase = ob + h * W_ + w4 * 4;

            #pragma unroll
            for (int kh = 0; kh < 3; kh++) {
                const int hh = h + kh - 1;                // -1..48
                const bool rok = (unsigned)hh < (unsigned)H_;

                #pragma unroll
                for (int kd = 0; kd < 3; kd++) {
                    const float* __restrict__ p =
                        s + kd * SPLANE + hh * W_ + w4 * 4;

                    float4 q = make_float4(0.f, 0.f, 0.f, 0.f);
                    float pw = 0.f, nx = 0.f;
                    if (rok) {
                        q = *reinterpret_cast<const float4*>(p);
                        if (w4 > 0)       pw = p[-1];     // input col 4w4-1
                        if (w4 < W4 - 1)  nx = p[4];      // input col 4w4+4
                    }

                    float* o = obase + ((kd * 3 + kh) * 3) * DHW;
                    *reinterpret_cast<float4*>(o) =
                        make_float4(pw, q.x, q.y, q.z);            // kw=0
                    *reinterpret_cast<float4*>(o + DHW) = q;       // kw=1
                    *reinterpret_cast<float4*>(o + 2 * DHW) =
                        make_float4(q.y, q.z, q.w, nx);            // kw=2
                }
            }
        }
        __syncthreads();   // protect smem before next tile overwrites it
    }
}

extern "C" void kernel_launch(void* const* d_in, const int* in_sizes, int n_in,
                              void* d_out, int out_size)
{
    const float* x = (const float*)d_in[0];
    float* out = (float*)d_out;

    dim3 grid(NCTAS);              // 1184 persistent CTAs (8 per SM)
    dim3 block(W4, 16);            // 192 threads
    unfold3d_kernel<<<grid, block>>>(x, out);
}

// round 10
// speedup vs baseline: 1.1015x; 1.0933x over previous
#include <cuda_runtime.h>
#include <cuda_bf16.h>
#include <cstdint>

// Unfold3d: x (B=4, C=32, D=16, H=48, W=48) fp32, K=3, PAD=1, STR=1, DIL=1.
// out[b][c*27 + kidx][d*HW + h*W + w] = x[b][c][d+kd-1][h+kh-1][w+kw-1] (0 OOB)
//
// R8: wave-quantization fix. 1024 CTAs, one per (d-pair, bc); each does
// EXACTLY 2 tiles (d = 2dp, 2dp+1). At 7 CTAs/SM (smem 27.6KB x 7 = 193KB)
// capacity = 1036 >= 1024 -> the whole grid is a single resident wave with
// perfectly balanced work (R7's 1184-CTA persistent grid had 864 CTAs doing
// 2 tiles and 320 doing 1 -> same tail as a second wave). Body = R5 structure:
// packed halo-free smem planes, predicated row/col edges, __stcs stores.

#define B_  4
#define C_  32
#define D_  16
#define H_  48
#define W_  48
#define HW  (H_ * W_)          // 2304
#define DHW (D_ * HW)          // 36864
#define W4  (W_ / 4)           // 12
#define SPLANE HW              // packed plane, 2304 floats
#define SMEM_FLOATS (3 * SPLANE)  // 6912 floats = 27648 B

#define NCTAS (8 * B_ * C_)    // 1024: (d-pair) x (b*c)

__global__ __launch_bounds__(192, 7) void unfold3d_kernel(
    const float* __restrict__ x, float* __restrict__ out)
{
    __shared__ float s[SMEM_FLOATS];

    const int dp = blockIdx.x & 7;      // d-pair index 0..7
    const int bc = blockIdx.x >> 3;     // 0..127

    const int w4 = threadIdx.x;         // 0..11
    const int hb = threadIdx.y;         // 0..15

    const float* __restrict__ xb = x + (size_t)bc * DHW;

    #pragma unroll 1
    for (int t = 0; t < 2; t++) {
        const int d = dp * 2 + t;       // 0..15

        if (t) __syncthreads();         // smem of previous tile fully consumed

        // ---- Phase 1: copy 3 planes (d-1, d, d+1) into packed smem ----
        #pragma unroll
        for (int p = 0; p < 3; p++) {
            const int dd = d + p - 1;
            float* __restrict__ sp = s + p * SPLANE;
            if ((unsigned)dd < (unsigned)D_) {
                const float* __restrict__ plane = xb + dd * HW;
                #pragma unroll
                for (int k = 0; k < 3; k++) {
                    const int r = hb + k * 16;
                    *reinterpret_cast<float4*>(sp + r * W_ + w4 * 4) =
                        *reinterpret_cast<const float4*>(
                            plane + r * W_ + w4 * 4);
                }
            } else {
                #pragma unroll
                for (int k = 0; k < 3; k++) {
                    const int r = hb + k * 16;
                    *reinterpret_cast<float4*>(sp + r * W_ + w4 * 4) =
                        make_float4(0.f, 0.f, 0.f, 0.f);
                }
            }
        }
        __syncthreads();

        // ---- Phase 2: 27 channel tiles, predicated edges ----
        float* __restrict__ ob = out + (size_t)bc * 27 * DHW + (size_t)d * HW;

        #pragma unroll
        for (int k = 0; k < 3; k++) {
            const int h = hb + k * 16;                    // 0..47
            float* __restrict__ obase = ob + h * W_ + w4 * 4;

            #pragma unroll
            for (int kh = 0; kh < 3; kh++) {
                const int hh = h + kh - 1;                // -1..48
                const bool rok = (unsigned)hh < (unsigned)H_;

                #pragma unroll
                for (int kd = 0; kd < 3; kd++) {
                    const float* __restrict__ p =
                        s + kd * SPLANE + hh * W_ + w4 * 4;

                    float4 q = make_float4(0.f, 0.f, 0.f, 0.f);
                    float pw = 0.f, nx = 0.f;
                    if (rok) {
                        q = *reinterpret_cast<const float4*>(p);
                        if (w4 > 0)       pw = p[-1];     // input col 4w4-1
                        if (w4 < W4 - 1)  nx = p[4];      // input col 4w4+4
                    }

                    float* o = obase + ((kd * 3 + kh) * 3) * DHW;
                    __stcs(reinterpret_cast<float4*>(o),
                           make_float4(pw, q.x, q.y, q.z));           // kw=0
                    __stcs(reinterpret_cast<float4*>(o + DHW), q);    // kw=1
                    __stcs(reinterpret_cast<float4*>(o + 2 * DHW),
                           make_float4(q.y, q.z, q.w, nx));           // kw=2
                }
            }
        }
    }
}

extern "C" void kernel_launch(void* const* d_in, const int* in_sizes, int n_in,
                              void* d_out, int out_size)
{
    const float* x = (const float*)d_in[0];
    float* out = (float*)d_out;

    dim3 grid(NCTAS);              // 1024 CTAs = one balanced resident wave
    dim3 block(W4, 16);            // 192 threads
    unfold3d_kernel<<<grid, block>>>(x, out);
}